// round 1
// baseline (speedup 1.0000x reference)
#include <cuda_runtime.h>
#include <cuda_bf16.h>

// DCT-II basis constants: Ak = cos(k*pi/16), F0 = 1/sqrt(8)
#define A1 0.98078528040323044f
#define A2 0.92387953251128674f
#define A3 0.83146961230254524f
#define A4 0.70710678118654752f
#define A5 0.55557023301960218f
#define A6 0.38268343236508978f
#define A7 0.19509032201612827f
#define F0 0.35355339059327373f

__global__ void __launch_bounds__(256, 2)
jpeg_dct_kernel(const float* __restrict__ img, const float* __restrict__ qf,
                float* __restrict__ out)
{
    // Orthonormal DCT-II matrix, fully constant -> folds to FFMA immediates
    const float C[8][8] = {
        { F0,      F0,      F0,      F0,      F0,      F0,      F0,      F0     },
        { .5f*A1,  .5f*A3,  .5f*A5,  .5f*A7, -.5f*A7, -.5f*A5, -.5f*A3, -.5f*A1},
        { .5f*A2,  .5f*A6, -.5f*A6, -.5f*A2, -.5f*A2, -.5f*A6,  .5f*A6,  .5f*A2},
        { .5f*A3, -.5f*A7, -.5f*A1, -.5f*A5,  .5f*A5,  .5f*A1,  .5f*A7, -.5f*A3},
        { .5f*A4, -.5f*A4, -.5f*A4,  .5f*A4,  .5f*A4, -.5f*A4, -.5f*A4,  .5f*A4},
        { .5f*A5, -.5f*A1,  .5f*A7,  .5f*A3, -.5f*A3, -.5f*A7,  .5f*A1, -.5f*A5},
        { .5f*A6, -.5f*A2,  .5f*A2, -.5f*A6, -.5f*A6,  .5f*A2, -.5f*A2,  .5f*A6},
        { .5f*A7, -.5f*A5,  .5f*A3, -.5f*A1,  .5f*A1, -.5f*A3,  .5f*A5, -.5f*A7},
    };
    // Luminance quantization table (the /100 and reciprocal fold at compile time)
    const float Qt[8][8] = {
        {16,11,10,16,24,40,51,61},
        {12,12,14,19,26,58,60,55},
        {14,13,16,24,40,57,69,56},
        {14,17,22,29,51,87,80,62},
        {18,22,37,56,68,109,103,77},
        {24,36,55,64,81,104,113,92},
        {49,64,78,87,103,121,120,101},
        {72,92,95,98,112,100,103,99},
    };

    int tid = blockIdx.x * 256 + threadIdx.x;   // 262144 threads total
    int w = tid & 127;          // block column (fastest -> coalescing)
    int h = (tid >> 7) & 127;   // block row
    int b = tid >> 14;          // batch

    const float* p = img + ((long)b << 20) + ((long)(h << 3) << 10) + (w << 3);

    // First pass: t[k][c] = sum_r C[k][r] * (x[r][c] - 128)
    float t[8][8];
#pragma unroll
    for (int k = 0; k < 8; ++k)
#pragma unroll
        for (int c = 0; c < 8; ++c) t[k][c] = 0.0f;

#pragma unroll
    for (int r = 0; r < 8; ++r) {
        float4 lo = *reinterpret_cast<const float4*>(p + r * 1024);
        float4 hi = *reinterpret_cast<const float4*>(p + r * 1024 + 4);
        float row[8] = {lo.x - 128.0f, lo.y - 128.0f, lo.z - 128.0f, lo.w - 128.0f,
                        hi.x - 128.0f, hi.y - 128.0f, hi.z - 128.0f, hi.w - 128.0f};
#pragma unroll
        for (int k = 0; k < 8; ++k)
#pragma unroll
            for (int c = 0; c < 8; ++c)
                t[k][c] = fmaf(C[k][r], row[c], t[k][c]);
    }

    // Quality factor scaling
    float q = qf[b];
    float factor = (q < 50.0f) ? (5000.0f / q) : (200.0f - 2.0f * q);
    float invF = 1.0f / factor;

    // Second pass + quantization scale + store.
    // out[b, k*8+l, h, w]: per-(k,l) plane stride = 128*128 = 16384
    float* op = out + ((long)b << 20) + (h << 7) + w;
#pragma unroll
    for (int k = 0; k < 8; ++k)
#pragma unroll
        for (int l = 0; l < 8; ++l) {
            float o = 0.0f;
#pragma unroll
            for (int m = 0; m < 8; ++m)
                o = fmaf(t[k][m], C[l][m], o);
            op[(long)((k << 3) + l) << 14] = o * (invF * (100.0f / Qt[k][l]));
        }
}

extern "C" void kernel_launch(void* const* d_in, const int* in_sizes, int n_in,
                              void* d_out, int out_size)
{
    // metadata order: image (16*1*1024*1024 fp32), quality_factor (16 fp32).
    // Guard against ordering surprises by picking the big tensor as the image.
    const float* img = (const float*)d_in[0];
    const float* qf  = (const float*)d_in[1];
    if (n_in >= 2 && in_sizes[0] < in_sizes[1]) {
        img = (const float*)d_in[1];
        qf  = (const float*)d_in[0];
    }
    float* out = (float*)d_out;

    // 16 * 128 * 128 = 262144 blocks, one thread each
    jpeg_dct_kernel<<<1024, 256>>>(img, qf, out);
}